// round 13
// baseline (speedup 1.0000x reference)
#include <cuda_runtime.h>
#include <math.h>
#include <stdint.h>

#define NB 4
#define NPTS 8192
#define NP 2048
#define NS 32
#define NCH 34
#define CSTRIDE (NP * NS) /* 65536 */
#define EPSF 1e-6f

#define NCELL 125           /* 5x5x5 cells of width 0.2 per batch */
#define BLK_WARPS 8
#define BLK_THREADS (BLK_WARPS * 32)
#define HITCAP 640          /* max in-ball hits per group (expected ~274, max ~350) */

// Scratch (device globals; no allocations).
__device__ int    g_cnt[NB * NCELL];
__device__ int    g_start[NB * (NCELL + 1)];
__device__ int    g_cur[NB * NCELL];
__device__ float4 g_bin[NB * NPTS];   // (x, y, z, bitcast(batch-local index))
__device__ float2 g_sxy[NB * NPTS];   // original-order SoA for epilogue gather
__device__ float  g_sz[NB * NPTS];

__device__ __forceinline__ int cell_of(float x, float y, float z) {
    int cx = min(4, (int)(x * 5.0f));
    int cy = min(4, (int)(y * 5.0f));
    int cz = min(4, (int)(z * 5.0f));
    return (cz * 5 + cy) * 5 + cx;
}

__device__ __forceinline__ unsigned rotl32(unsigned x, int d) {
    return (x << d) | (x >> (32 - d));
}

// jax.random.uniform(key(42), (4,1,2048,32)) at flat index i -> (u-0.5)*2pi.
// threefry2x32 partitionable: x0=hi(count)=0, x1=lo(count)=i, key=(0,42),
// 32-bit draw = out0 ^ out1.
__device__ float jax_rand_angle(unsigned i) {
    const unsigned ks0 = 0u, ks1 = 42u, ks2 = 0u ^ 42u ^ 0x1BD11BDAu;
    unsigned x0 = 0u + ks0;
    unsigned x1 = i + ks1;
#define TF_RND(r) { x0 += x1; x1 = rotl32(x1, (r)); x1 ^= x0; }
    TF_RND(13) TF_RND(15) TF_RND(26) TF_RND(6)  x0 += ks1; x1 += ks2 + 1u;
    TF_RND(17) TF_RND(29) TF_RND(16) TF_RND(24) x0 += ks2; x1 += ks0 + 2u;
    TF_RND(13) TF_RND(15) TF_RND(26) TF_RND(6)  x0 += ks0; x1 += ks1 + 3u;
    TF_RND(17) TF_RND(29) TF_RND(16) TF_RND(24) x0 += ks1; x1 += ks2 + 4u;
    TF_RND(13) TF_RND(15) TF_RND(26) TF_RND(6)  x0 += ks2; x1 += ks0 + 5u;
#undef TF_RND
    unsigned bits = x0 ^ x1;
    float u = __uint_as_float((bits >> 9) | 0x3F800000u) - 1.0f;
    u = fmaxf(u, 0.0f);
    return (u - 0.5f) * 6.283185307179586f;
}

__global__ void zero_kernel() {
    int i = blockIdx.x * blockDim.x + threadIdx.x;
    if (i < NB * NCELL) g_cnt[i] = 0;
}

__global__ void count_kernel(const float* __restrict__ xyz) {
    int i = blockIdx.x * blockDim.x + threadIdx.x;
    if (i < NB * NPTS) {
        float x = xyz[3 * i + 0];
        float y = xyz[3 * i + 1];
        float z = xyz[3 * i + 2];
        g_sxy[i] = make_float2(x, y);
        g_sz[i] = z;
        int b = i >> 13; // / NPTS
        atomicAdd(&g_cnt[b * NCELL + cell_of(x, y, z)], 1);
    }
}

__global__ void prefix_kernel() {
    // 512 threads: 4 batches x 128 slots. Hillis-Steele inclusive scan.
    __shared__ int s[NB * 128];
    int t = threadIdx.x;
    int b = t >> 7, j = t & 127;
    s[t] = (j < NCELL) ? g_cnt[b * NCELL + j] : 0;
    __syncthreads();
    for (int d = 1; d < 128; d <<= 1) {
        int add = (j >= d) ? s[t - d] : 0;
        __syncthreads();
        s[t] += add;
        __syncthreads();
    }
    if (j <= NCELL) {
        int st = (j == 0) ? 0 : s[t - 1];
        g_start[b * (NCELL + 1) + j] = st;
        if (j < NCELL) g_cur[b * NCELL + j] = st;
    }
}

__global__ void scatter_kernel(const float* __restrict__ xyz) {
    int i = blockIdx.x * blockDim.x + threadIdx.x;
    if (i < NB * NPTS) {
        float x = xyz[3 * i + 0];
        float y = xyz[3 * i + 1];
        float z = xyz[3 * i + 2];
        int b = i >> 13;
        int pos = atomicAdd(&g_cur[b * NCELL + cell_of(x, y, z)], 1);
        g_bin[b * NPTS + pos] =
            make_float4(x, y, z, __int_as_float(i - b * NPTS));
    }
}

__global__ void __launch_bounds__(BLK_THREADS, 8)
qgq_kernel(const float* __restrict__ new_xyz,
           float* __restrict__ out)
{
    __shared__ int   hitbuf[BLK_WARPS * HITCAP];
    __shared__ int   sortbuf[BLK_WARPS * 32];
    __shared__ float angbuf[BLK_WARPS * 32];
    __shared__ int   idxbuf[BLK_WARPS * 32];

    const int warp = threadIdx.x >> 5;
    const int lane = threadIdx.x & 31;
    const int g = blockIdx.x * BLK_WARPS + warp;
    const int b = g >> 11;
    const int p = g & (NP - 1);

    int*   hb    = hitbuf + warp * HITCAP;
    int*   srt   = sortbuf + warp * 32;
    float* myang = angbuf + warp * 32;
    int*   myidx = idxbuf + warp * 32;

    const float cx = new_xyz[((size_t)b * NP + p) * 3 + 0];
    const float cy = new_xyz[((size_t)b * NP + p) * 3 + 1];
    const float cz = new_xyz[((size_t)b * NP + p) * 3 + 2];

    // ---- gather ALL in-ball hits from the 27-cell neighborhood ----
    const float R2 = (float)(0.2 * 0.2);
    const unsigned ltmask = (1u << lane) - 1u;
    const float4* __restrict__ bin = g_bin + (size_t)b * NPTS;
    const int* __restrict__ starts = g_start + b * (NCELL + 1);

    int cbx = min(4, (int)(cx * 5.0f));
    int cby = min(4, (int)(cy * 5.0f));
    int cbz = min(4, (int)(cz * 5.0f));
    int xlo = max(0, cbx - 1), xhi = min(4, cbx + 1);
    int ylo = max(0, cby - 1), yhi = min(4, cby + 1);
    int zlo = max(0, cbz - 1), zhi = min(4, cbz + 1);

    int K = 0;
    for (int zb = zlo; zb <= zhi; zb++) {
        for (int yb = ylo; yb <= yhi; yb++) {
            int row = (zb * 5 + yb) * 5;
            int s = starts[row + xlo];
            int e = starts[row + xhi + 1];
            for (int i0 = s; i0 < e; i0 += 32) {
                int i = i0 + lane;
                bool valid = i < e;
                float4 pt = __ldg(&bin[valid ? i : (e - 1)]);
                float dx = __fadd_rn(cx, -pt.x);
                float dy = __fadd_rn(cy, -pt.y);
                float dz = __fadd_rn(cz, -pt.z);
                float d2 = __fadd_rn(
                    __fadd_rn(__fmul_rn(dx, dx), __fmul_rn(dy, dy)),
                    __fmul_rn(dz, dz));
                bool hit = valid && (d2 < R2);
                unsigned m = __ballot_sync(0xFFFFFFFFu, hit);
                if (hit) {
                    int pos = K + __popc(m & ltmask);
                    hb[pos] = __float_as_int(pt.w);
                }
                K += __popc(m);
            }
        }
    }
    __syncwarp();

    // ---- select the NS smallest indices among the K hits ----
    int T = 0x7FFFFFFF;
    if (K > NS) {
        // smallest T with |{idx < T}| >= NS  (indices distinct -> exactly NS)
        int lo = 0, hi = NPTS;
        while (hi - lo > 1) {
            int mid = (lo + hi) >> 1;
            int c = 0;
            for (int j = lane; j < K; j += 32) c += (hb[j] < mid) ? 1 : 0;
            c = __reduce_add_sync(0xFFFFFFFFu, c);
            if (c >= NS) hi = mid; else lo = mid;
        }
        T = hi;
    }
    // compact elements < T into myidx (C = min(K, NS) elements, unordered)
    int C = 0;
    for (int j0 = 0; j0 < K; j0 += 32) {
        int j = j0 + lane;
        bool tk = (j < K) && (hb[j] < T);
        unsigned m = __ballot_sync(0xFFFFFFFFu, tk);
        if (tk) myidx[C + __popc(m & ltmask)] = hb[j];
        C += __popc(m);
    }
    __syncwarp();
    // sort the C indices ascending (rank-count; dummies INT_MAX sort last)
    int cand = (lane < C) ? myidx[lane] : 0x7FFFFFFF;
    srt[lane] = cand;
    __syncwarp();
    int rank = 0;
#pragma unroll
    for (int t = 0; t < 32; t++) {
        int v = srt[t];
        rank += ((v < cand) || (v == cand && t < lane)) ? 1 : 0;
    }
    myidx[rank] = cand;
    __syncwarp();
    int nb = myidx[(lane < C) ? lane : 0];
    __syncwarp();

    // rel = grouped point - center
    float2 nbxy = __ldg(&g_sxy[(size_t)b * NPTS + nb]);
    float  nbz  = __ldg(&g_sz[(size_t)b * NPTS + nb]);
    float rx = __fadd_rn(nbxy.x, -cx);
    float ry = __fadd_rn(nbxy.y, -cy);
    float rz = __fadd_rn(nbz, -cz);

    // ---- p1 = normalize(center) (warp-uniform) ----
    float cn = sqrtf(cx * cx + cy * cy + cz * cz);
    float den1 = cn + EPSF;
    float px = __fdiv_rn(cx, den1);
    float py = __fdiv_rn(cy, den1);
    float pz = __fdiv_rn(cz, den1);

    // ---- _project_one ----
    float pn = sqrtf(px * px + py * py + pz * pz);
    float den2 = pn + EPSF;
    float p2x = __fdiv_rn(px, den2);
    float p2y = __fdiv_rn(py, den2);
    float p2z = __fdiv_rn(pz, den2);
    bool colin = fabsf(p2x) > 0.999f;
    float rfx = colin ? (-p2y * p2x) : (1.0f - p2x * p2x);
    float rfy = colin ? (1.0f - p2y * p2y) : (-p2x * p2y);
    float rfz = colin ? (-p2y * p2z) : (-p2x * p2z);
    float rn = sqrtf(rfx * rfx + rfy * rfy + rfz * rfz);
    float den3 = rn + EPSF;
    float ix = __fdiv_rn(rfx, den3);
    float iy = __fdiv_rn(rfy, den3);
    float iz = __fdiv_rn(rfz, den3);

    // ---- project rel onto plane orthogonal to p1, get angle ----
    float dotp = px * rx + py * ry + pz * rz;
    float vx = rx - dotp * px;
    float vy = ry - dotp * py;
    float vz = rz - dotp * pz;
    float vn = sqrtf(vx * vx + vy * vy + vz * vz);
    float den4 = vn + EPSF;
    float qx = __fdiv_rn(vx, den4);
    float qy = __fdiv_rn(vy, den4);
    float qz = __fdiv_rn(vz, den4);
    float pr2 = qx * qx + qy * qy + qz * qz;
    float sinv = (iy * qz - iz * qy) * px + (iz * qx - ix * qz) * py +
                 (ix * qy - iy * qx) * pz;
    float cosv = ix * qx + iy * qy + iz * qz;
    float ang = atan2f(sinv, cosv);
    if (pr2 < 1e-12f) {
        ang = jax_rand_angle(((unsigned)(b * NP + p)) * NS + (unsigned)lane);
    }

    // ---- stable argsort by angle (tie-break by slot) ----
    myang[lane] = ang;
    __syncwarp();
    int arank = 0;
#pragma unroll
    for (int t = 0; t < 32; t++) {
        float a = myang[t];
        arank += ((a < ang) || (a == ang && t < lane)) ? 1 : 0;
    }
    __syncwarp();
    myidx[arank] = lane;
    __syncwarp();
    int src = myidx[lane];
    rx = __shfl_sync(0xFFFFFFFFu, rx, src);
    ry = __shfl_sync(0xFFFFFFFFu, ry, src);
    rz = __shfl_sync(0xFFFFFFFFu, rz, src);

    // ---- invariance features ----
    float d2s = rx * rx + ry * ry + rz * rz;
    float norm2 = sqrtf(d2s + 1e-12f);
    float cosang = __fdiv_rn(px * rx + py * ry + pz * rz, norm2);
    cosang = fminf(fmaxf(cosang, -1.0f + EPSF), 1.0f - EPSF);
    float angle = acosf(cosang);

    // ---- quaternion ----
    float dist = sqrtf(d2s);
    float den5 = dist + EPSF;
    float theta = __fmul_rn(__fdiv_rn(dist, 0.2f), 1.5707963267948966f);
    float q0 = cosf(theta);
    float st = sinf(theta);
    float q1 = st * __fdiv_rn(rx, den5);
    float q2 = st * __fdiv_rn(ry, den5);
    float q3 = st * __fdiv_rn(rz, den5);

    // ---- output: (B, 34, P, 32) ----
    float* ob = out + (size_t)b * NCH * CSTRIDE + (size_t)p * NS + lane;
    ob[0] = norm2;
    ob[(size_t)CSTRIDE] = angle;
    float q[4] = {q0, q1, q2, q3};
#pragma unroll
    for (int c = 0; c < 4; c++) {
#pragma unroll
        for (int m = 0; m < 8; m++) {
            float v = __shfl_sync(0xFFFFFFFFu, q[c], (lane + m) & 31);
            ob[(size_t)(2 + c * 8 + m) * CSTRIDE] = v;
        }
    }
}

extern "C" void kernel_launch(void* const* d_in, const int* in_sizes, int n_in,
                              void* d_out, int out_size) {
    const float* xyz = (const float*)d_in[0];
    const float* new_xyz = (const float*)d_in[1];
    float* out = (float*)d_out;

    zero_kernel<<<(NB * NCELL + 511) / 512, 512>>>();
    count_kernel<<<(NB * NPTS + 255) / 256, 256>>>(xyz);
    prefix_kernel<<<1, NB * 128>>>();
    scatter_kernel<<<(NB * NPTS + 255) / 256, 256>>>(xyz);

    const int nblocks = (NB * NP) / BLK_WARPS; // 1024
    qgq_kernel<<<nblocks, BLK_THREADS>>>(new_xyz, out);
}